// round 15
// baseline (speedup 1.0000x reference)
#include <cuda_runtime.h>
#include <cstdint>

#define N_NODE 100000
#define N_NETS 20000
#define NEDGE  200000
// H_NODE=64, H_NET=32, H_PIN=16, O_NODE=32, O_NET=64

// ---------------- scratch (device globals; zero-init at load) ----------------
// INVARIANT: g_cnt, g_cursor, g_degN are all-zero at kernel_launch entry;
// every call restores this at its end (k_tail), so replays are identical.
__device__ __align__(16) float g_T[N_NETS * 512];    // [n][p*32+o]  41MB
__device__ __align__(16) float g_Bias[N_NETS * 32];
__device__ __align__(16) float g_agg[N_NETS * 64];
__device__ __align__(16) float g_degN[N_NODE];
__device__ __align__(16) int   g_cnt[N_NETS];
__device__ __align__(16) int   g_cursor[N_NETS];
__device__ __align__(16) int   g_start[N_NETS];
__device__ __align__(16) int   g_sEdge[NEDGE];
__device__ __align__(16) int   g_sNode[NEDGE];
__device__ __align__(16) float g_B[32 * 512];        // W2 rearranged: [i][p*32+o]

__device__ __forceinline__ void red_add_v4(float* addr, float4 v) {
    asm volatile("red.global.add.v4.f32 [%0], {%1, %2, %3, %4};"
                 :: "l"(addr), "f"(v.x), "f"(v.y), "f"(v.z), "f"(v.w)
                 : "memory");
}

// ============ 1. fused: degrees | zero out-region | W2 rearrange | bias ============
__global__ void __launch_bounds__(256) k_degzero(const int* __restrict__ edge_node,
                                                 const int* __restrict__ edge_net,
                                                 const float* __restrict__ W2,
                                                 const float* __restrict__ net_feat,
                                                 const float* __restrict__ b2,
                                                 float* __restrict__ out) {
    int b = blockIdx.x;
    int t = threadIdx.x;
    if (b < 782) {
        int e = b * 256 + t;
        if (e >= NEDGE) return;
        atomicAdd(&g_degN[edge_node[e]], 1.0f);
        atomicAdd(&g_cnt[edge_net[e]], 1);
    } else if (b < 3907) {
        int i = (b - 782) * 256 + t;
        if (i < 800000)
            ((float4*)out)[i] = make_float4(0.f, 0.f, 0.f, 0.f);
    } else if (b < 3971) {
        int idx = (b - 3907) * 256 + t;
        if (idx < 16384) {
            int i = idx >> 9;
            int c = idx & 511;
            int p = c >> 5, o = c & 31;
            g_B[idx] = W2[p * 1024 + i * 32 + o];
        }
    } else {
        __shared__ float b2s[1024];
        for (int k = t; k < 1024; k += 256) b2s[k] = b2[k];
        __syncthreads();
        int idx = (b - 3971) * 256 + t;
        int n = idx >> 5, o = idx & 31;
        if (n >= N_NETS) return;
        float acc = 0.f;
#pragma unroll
        for (int i = 0; i < 32; i++) acc += net_feat[n * 32 + i] * b2s[i * 32 + o];
        g_Bias[n * 32 + o] = acc;
    }
}

// ============ 2. single-block exclusive scan (register-resident) ============
__global__ void __launch_bounds__(1024) k_scan() {
    __shared__ int wsum[32];
    int t = threadIdx.x;
    int lane = t & 31, wid = t >> 5;
    int base = t * 20;
    int c[20];
    int sum = 0;
#pragma unroll
    for (int k = 0; k < 20; k++) {
        int i = base + k;
        c[k] = (i < N_NETS) ? g_cnt[i] : 0;
        sum += c[k];
    }
    int v = sum;
#pragma unroll
    for (int d = 1; d < 32; d <<= 1) {
        int u = __shfl_up_sync(0xffffffffu, v, d);
        if (lane >= d) v += u;
    }
    if (lane == 31) wsum[wid] = v;
    __syncthreads();
    if (wid == 0) {
        int w = wsum[lane];
#pragma unroll
        for (int d = 1; d < 32; d <<= 1) {
            int u = __shfl_up_sync(0xffffffffu, w, d);
            if (lane >= d) w += u;
        }
        wsum[lane] = w;
    }
    __syncthreads();
    int run = (v - sum) + (wid ? wsum[wid - 1] : 0);
#pragma unroll
    for (int k = 0; k < 20; k++) {
        int i = base + k;
        if (i < N_NETS) g_start[i] = run;
        run += c[k];
    }
}

// ============ 3. fused mid: T GEMM (double-buffered B) | scatter ============
__global__ void __launch_bounds__(256) k_mid(const float* __restrict__ net_feat,
                                             const int* __restrict__ edge_node,
                                             const int* __restrict__ edge_net) {
    extern __shared__ float sm[];
    int b = blockIdx.x;
    int t = threadIdx.x;

    if (b < 625) {
        float* Bs = sm;                           // 16384 floats (64KB)
        float2* nfp = (float2*)(sm + 16384);      // [i*32+r] dup-packed (8KB)
        for (int k = t; k < 4096; k += 256)
            ((float4*)Bs)[k] = ((const float4*)g_B)[k];
        int n0 = b * 32;
        for (int k = t; k < 1024; k += 256) {
            int i = k & 31, r = k >> 5;
            float s = net_feat[(n0 + r) * 32 + i];
            nfp[i * 32 + r] = make_float2(s, s);
        }
        __syncthreads();

        int c  = t & 63;   // f4 cols c and c+64
        int rg = t >> 6;   // row group 0..3: rows rg*8 .. rg*8+7
        const float4* B4 = (const float4*)Bs;

        unsigned long long acc[32];
#pragma unroll
        for (int k = 0; k < 32; k++) acc[k] = 0ull;

        float4 bA = B4[c];
        float4 bB = B4[64 + c];
#pragma unroll
        for (int i = 0; i < 32; i++) {
            float4 nA = bA, nB = bB;
            if (i < 31) {
                nA = B4[(i + 1) * 128 + c];
                nB = B4[(i + 1) * 128 + 64 + c];
            }
            unsigned long long a01, a23, b01, b23;
            asm("mov.b64 %0, {%1, %2};" : "=l"(a01) : "f"(bA.x), "f"(bA.y));
            asm("mov.b64 %0, {%1, %2};" : "=l"(a23) : "f"(bA.z), "f"(bA.w));
            asm("mov.b64 %0, {%1, %2};" : "=l"(b01) : "f"(bB.x), "f"(bB.y));
            asm("mov.b64 %0, {%1, %2};" : "=l"(b23) : "f"(bB.z), "f"(bB.w));
            const ulonglong2* SPi = (const ulonglong2*)(nfp + i * 32 + rg * 8);
            ulonglong2 s0 = SPi[0], s1 = SPi[1], s2 = SPi[2], s3 = SPi[3];
#pragma unroll
            for (int j = 0; j < 4; j++) {
                ulonglong2 sv = (j == 0) ? s0 : (j == 1) ? s1 : (j == 2) ? s2 : s3;
                asm("fma.rn.f32x2 %0, %1, %2, %0;" : "+l"(acc[(2*j)  *4+0]) : "l"(sv.x), "l"(a01));
                asm("fma.rn.f32x2 %0, %1, %2, %0;" : "+l"(acc[(2*j)  *4+1]) : "l"(sv.x), "l"(a23));
                asm("fma.rn.f32x2 %0, %1, %2, %0;" : "+l"(acc[(2*j)  *4+2]) : "l"(sv.x), "l"(b01));
                asm("fma.rn.f32x2 %0, %1, %2, %0;" : "+l"(acc[(2*j)  *4+3]) : "l"(sv.x), "l"(b23));
                asm("fma.rn.f32x2 %0, %1, %2, %0;" : "+l"(acc[(2*j+1)*4+0]) : "l"(sv.y), "l"(a01));
                asm("fma.rn.f32x2 %0, %1, %2, %0;" : "+l"(acc[(2*j+1)*4+1]) : "l"(sv.y), "l"(a23));
                asm("fma.rn.f32x2 %0, %1, %2, %0;" : "+l"(acc[(2*j+1)*4+2]) : "l"(sv.y), "l"(b01));
                asm("fma.rn.f32x2 %0, %1, %2, %0;" : "+l"(acc[(2*j+1)*4+3]) : "l"(sv.y), "l"(b23));
            }
            bA = nA;
            bB = nB;
        }

#pragma unroll
        for (int r = 0; r < 8; r++) {
            float4 o0, o1;
            asm("mov.b64 {%0, %1}, %2;" : "=f"(o0.x), "=f"(o0.y) : "l"(acc[r * 4 + 0]));
            asm("mov.b64 {%0, %1}, %2;" : "=f"(o0.z), "=f"(o0.w) : "l"(acc[r * 4 + 1]));
            asm("mov.b64 {%0, %1}, %2;" : "=f"(o1.x), "=f"(o1.y) : "l"(acc[r * 4 + 2]));
            asm("mov.b64 {%0, %1}, %2;" : "=f"(o1.z), "=f"(o1.w) : "l"(acc[r * 4 + 3]));
            size_t row = (size_t)(n0 + rg * 8 + r) * 128;
            ((float4*)g_T)[row + c]      = o0;
            ((float4*)g_T)[row + 64 + c] = o1;
        }
    } else {
        int e = (b - 625) * 256 + t;
        if (e >= NEDGE) return;
        int n = edge_net[e];
        int pos = g_start[n] + atomicAdd(&g_cursor[n], 1);
        g_sEdge[pos] = e;
        g_sNode[pos] = edge_node[e];
    }
}

// ============ 4. edge (warp-per-net, register-cached T row) + rel-1 segment sum ============
// blocks [0,2500): warp per net; 8-lane group holds full T row in regs, 4 edges/iter.
// blocks [2500,5000): warp-per-net segment sum (x4 unrolled).
__global__ void __launch_bounds__(256) k_edgeagg(const float* __restrict__ pin_feat,
                                                 const float* __restrict__ node_feat,
                                                 float* __restrict__ out) {
    int b = blockIdx.x;
    int t = threadIdx.x;
    int lane = t & 31;
    if (b < 2500) {
        int n = (b * 256 + t) >> 5;               // 20000 warps = 20000 nets
        int g = lane >> 3, j = lane & 7;
        int start = g_start[n], cnt = g_cnt[n];
        if (cnt == 0) return;

        // T row + bias live across the whole edge loop -> genuinely register-resident
        const float4* Trow = ((const float4*)g_T) + (size_t)n * 128;
        float4 Tr[16];
#pragma unroll
        for (int q = 0; q < 16; q++) Tr[q] = Trow[q * 8 + j];
        float4 bias = ((const float4*)g_Bias)[n * 8 + j];

        for (int base = 0; base < cnt; base += 4) {
            int idx = base + g;                   // group g takes edge base+g
            if (idx < cnt) {
                int s = start + idx;
                int v = g_sNode[s];
                int e = g_sEdge[s];
                const float4* pin4 = ((const float4*)pin_feat) + (size_t)e * 4;
                float4 acc = bias;
#pragma unroll
                for (int q = 0; q < 4; q++) {
                    float4 p = pin4[q];
                    float4 t0 = Tr[4 * q + 0];
                    float4 t1 = Tr[4 * q + 1];
                    float4 t2 = Tr[4 * q + 2];
                    float4 t3 = Tr[4 * q + 3];
                    acc.x += p.x * t0.x + p.y * t1.x + p.z * t2.x + p.w * t3.x;
                    acc.y += p.x * t0.y + p.y * t1.y + p.z * t2.y + p.w * t3.y;
                    acc.z += p.x * t0.z + p.y * t1.z + p.z * t2.z + p.w * t3.z;
                    acc.w += p.x * t0.w + p.y * t1.w + p.z * t2.w + p.w * t3.w;
                }
                red_add_v4(out + (size_t)v * 32 + j * 4, acc);
            }
        }
    } else {
        int n = ((b - 2500) * 256 + t) >> 5;
        if (n >= N_NETS) return;
        int start = g_start[n], cnt = g_cnt[n];
        float ax = 0.f, ay = 0.f;
        const float2* nf2 = (const float2*)node_feat;
        int p = 0;
        while (p < cnt) {
            int m = min(cnt - p, 32);
            int v = 0; float scl = 0.f;           // lanes >= m: v=0, scl=0 (safe)
            if (lane < m) {
                v = g_sNode[start + p + lane];
                scl = rsqrtf(fmaxf(g_degN[v], 1.0f));
            }
            int mm = (m + 3) & ~3;
            for (int k = 0; k < mm; k += 4) {
                int v0 = __shfl_sync(0xffffffffu, v, k);
                int v1 = __shfl_sync(0xffffffffu, v, k + 1);
                int v2 = __shfl_sync(0xffffffffu, v, k + 2);
                int v3 = __shfl_sync(0xffffffffu, v, k + 3);
                float s0 = __shfl_sync(0xffffffffu, scl, k);
                float s1 = __shfl_sync(0xffffffffu, scl, k + 1);
                float s2 = __shfl_sync(0xffffffffu, scl, k + 2);
                float s3 = __shfl_sync(0xffffffffu, scl, k + 3);
                float2 x0 = nf2[(size_t)v0 * 32 + lane];
                float2 x1 = nf2[(size_t)v1 * 32 + lane];
                float2 x2 = nf2[(size_t)v2 * 32 + lane];
                float2 x3 = nf2[(size_t)v3 * 32 + lane];
                ax += s0 * x0.x + s1 * x1.x + s2 * x2.x + s3 * x3.x;
                ay += s0 * x0.y + s1 * x1.y + s2 * x2.y + s3 * x3.y;
            }
            p += m;
        }
        float si = rsqrtf(fmaxf((float)cnt, 1.0f));
        ((float2*)g_agg)[n * 32 + lane] = make_float2(ax * si, ay * si);
    }
}

// ============ 5. tail: net_out GEMM | finalize (+restore zero-invariant) ============
__global__ void __launch_bounds__(256) k_tail(const float* __restrict__ W1,
                                              const float* __restrict__ b1,
                                              const float* __restrict__ b_nn,
                                              float* __restrict__ out) {
    int b = blockIdx.x;
    int t = threadIdx.x;
    if (b < 2500) {
        __shared__ float W1s[64 * 64];
        __shared__ float b1s[64];
        for (int k = t; k < 4096; k += 256) W1s[k] = W1[k];
        if (t < 64) b1s[t] = b1[t];
        __syncthreads();
        int lane = t & 31;
        int n = b * 8 + (t >> 5);
        if (n >= N_NETS) return;
        float* net_out = out + (size_t)N_NODE * 32;
        float a0 = g_agg[n * 64 + lane];
        float a1 = g_agg[n * 64 + 32 + lane];
        float acc0 = b1s[lane], acc1 = b1s[32 + lane];
#pragma unroll
        for (int k = 0; k < 32; k++) {
            float r = __shfl_sync(0xffffffffu, a0, k);
            acc0 += r * W1s[k * 64 + lane];
            acc1 += r * W1s[k * 64 + 32 + lane];
        }
#pragma unroll
        for (int k = 0; k < 32; k++) {
            float r = __shfl_sync(0xffffffffu, a1, k);
            acc0 += r * W1s[(k + 32) * 64 + lane];
            acc1 += r * W1s[(k + 32) * 64 + 32 + lane];
        }
        net_out[n * 64 + lane]      = acc0;
        net_out[n * 64 + 32 + lane] = acc1;
    } else if (b < 5625) {
        int idx = (b - 2500) * 256 + t;
        if (idx >= N_NODE * 8) return;
        int v = idx >> 3, j = idx & 7;
        float dn = g_degN[v];                 // warp-convergent read before j==0 store
        float inv = 1.0f / fmaxf(dn, 1.0f);
        float4 o = ((float4*)out)[idx];
        float4 bn = ((const float4*)b_nn)[j];
        o.x = o.x * inv + bn.x;
        o.y = o.y * inv + bn.y;
        o.z = o.z * inv + bn.z;
        o.w = o.w * inv + bn.w;
        ((float4*)out)[idx] = o;
        if (j == 0) g_degN[v] = 0.0f;         // restore invariant
    } else {
        int i = (b - 5625) * 256 + t;         // 5000 f4 each
        float4 z = make_float4(0.f, 0.f, 0.f, 0.f);
        if (i < 5000)       ((float4*)g_cnt)[i] = z;
        else if (i < 10000) ((float4*)g_cursor)[i - 5000] = z;
    }
}

extern "C" void kernel_launch(void* const* d_in, const int* in_sizes, int n_in,
                              void* d_out, int out_size) {
    const float* node_feat = (const float*)d_in[0];
    const float* net_feat  = (const float*)d_in[1];
    const float* pin_feat  = (const float*)d_in[2];
    const int*   edge_node = (const int*)d_in[3];
    const int*   edge_net  = (const int*)d_in[4];
    const float* W1   = (const float*)d_in[5];
    const float* b1   = (const float*)d_in[6];
    const float* W2   = (const float*)d_in[7];
    const float* b2   = (const float*)d_in[8];
    const float* b_nn = (const float*)d_in[9];
    float* out = (float*)d_out;

    cudaFuncSetAttribute(k_mid, cudaFuncAttributeMaxDynamicSharedMemorySize, 73728);

    k_degzero<<<6471, 256>>>(edge_node, edge_net, W2, net_feat, b2, out);
    k_scan<<<1, 1024>>>();
    k_mid<<<1407, 256, 73728>>>(net_feat, edge_node, edge_net);
    k_edgeagg<<<5000, 256>>>(pin_feat, node_feat, out);
    k_tail<<<5665, 256>>>(W1, b1, b_nn, out);
}

// round 17
// speedup vs baseline: 1.2702x; 1.2702x over previous
#include <cuda_runtime.h>
#include <cstdint>

#define N_NODE 100000
#define N_NETS 20000
#define NEDGE  200000
// H_NODE=64, H_NET=32, H_PIN=16, O_NODE=32, O_NET=64

// ---------------- scratch (device globals; zero-init at load) ----------------
// INVARIANT: g_cnt, g_cursor, g_degN are all-zero at kernel_launch entry;
// every call restores this at its end (k_tail), so replays are identical.
__device__ __align__(16) float g_T[N_NETS * 512];    // [n][p*32+o]  41MB
__device__ __align__(16) float g_Bias[N_NETS * 32];
__device__ __align__(16) float g_agg[N_NETS * 64];
__device__ __align__(16) float g_degN[N_NODE];
__device__ __align__(16) int   g_cnt[N_NETS];
__device__ __align__(16) int   g_cursor[N_NETS];
__device__ __align__(16) int   g_start[N_NETS];
__device__ __align__(16) int   g_sEdge[NEDGE];
__device__ __align__(16) int   g_sNode[NEDGE];
__device__ __align__(16) int   g_sNet[NEDGE];
__device__ __align__(16) float g_B[32 * 512];        // W2 rearranged: [i][p*32+o]

__device__ __forceinline__ void red_add_v4(float* addr, float4 v) {
    asm volatile("red.global.add.v4.f32 [%0], {%1, %2, %3, %4};"
                 :: "l"(addr), "f"(v.x), "f"(v.y), "f"(v.z), "f"(v.w)
                 : "memory");
}

// ============ 1. fused: degrees | zero out-region | W2 rearrange | bias ============
__global__ void __launch_bounds__(256) k_degzero(const int* __restrict__ edge_node,
                                                 const int* __restrict__ edge_net,
                                                 const float* __restrict__ W2,
                                                 const float* __restrict__ net_feat,
                                                 const float* __restrict__ b2,
                                                 float* __restrict__ out) {
    int b = blockIdx.x;
    int t = threadIdx.x;
    if (b < 782) {
        int e = b * 256 + t;
        if (e >= NEDGE) return;
        atomicAdd(&g_degN[edge_node[e]], 1.0f);
        atomicAdd(&g_cnt[edge_net[e]], 1);
    } else if (b < 3907) {
        int i = (b - 782) * 256 + t;
        if (i < 800000)
            ((float4*)out)[i] = make_float4(0.f, 0.f, 0.f, 0.f);
    } else if (b < 3971) {
        int idx = (b - 3907) * 256 + t;
        if (idx < 16384) {
            int i = idx >> 9;
            int c = idx & 511;
            int p = c >> 5, o = c & 31;
            g_B[idx] = W2[p * 1024 + i * 32 + o];
        }
    } else {
        __shared__ float b2s[1024];
        for (int k = t; k < 1024; k += 256) b2s[k] = b2[k];
        __syncthreads();
        int idx = (b - 3971) * 256 + t;
        int n = idx >> 5, o = idx & 31;
        if (n >= N_NETS) return;
        float acc = 0.f;
#pragma unroll
        for (int i = 0; i < 32; i++) acc += net_feat[n * 32 + i] * b2s[i * 32 + o];
        g_Bias[n * 32 + o] = acc;
    }
}

// ============ 2. single-block exclusive scan (register-resident) ============
__global__ void __launch_bounds__(1024) k_scan() {
    cudaGridDependencySynchronize();          // PDL: wait for k_degzero's atomics
    __shared__ int wsum[32];
    int t = threadIdx.x;
    int lane = t & 31, wid = t >> 5;
    int base = t * 20;
    int c[20];
    int sum = 0;
#pragma unroll
    for (int k = 0; k < 20; k++) {
        int i = base + k;
        c[k] = (i < N_NETS) ? g_cnt[i] : 0;
        sum += c[k];
    }
    int v = sum;
#pragma unroll
    for (int d = 1; d < 32; d <<= 1) {
        int u = __shfl_up_sync(0xffffffffu, v, d);
        if (lane >= d) v += u;
    }
    if (lane == 31) wsum[wid] = v;
    __syncthreads();
    if (wid == 0) {
        int w = wsum[lane];
#pragma unroll
        for (int d = 1; d < 32; d <<= 1) {
            int u = __shfl_up_sync(0xffffffffu, w, d);
            if (lane >= d) w += u;
        }
        wsum[lane] = w;
    }
    __syncthreads();
    int run = (v - sum) + (wid ? wsum[wid - 1] : 0);
#pragma unroll
    for (int k = 0; k < 20; k++) {
        int i = base + k;
        if (i < N_NETS) g_start[i] = run;
        run += c[k];
    }
}

// ============ 3. fused mid: T GEMM (double-buffered B) | scatter ============
__global__ void __launch_bounds__(256) k_mid(const float* __restrict__ net_feat,
                                             const int* __restrict__ edge_node,
                                             const int* __restrict__ edge_net) {
    extern __shared__ float sm[];
    int b = blockIdx.x;
    int t = threadIdx.x;

    if (b < 625) {
        cudaGridDependencySynchronize();      // PDL: g_B ready (transitively via k_scan)
        float* Bs = sm;                           // 16384 floats (64KB)
        float2* nfp = (float2*)(sm + 16384);      // [i*32+r] dup-packed (8KB)
        for (int k = t; k < 4096; k += 256)
            ((float4*)Bs)[k] = ((const float4*)g_B)[k];
        int n0 = b * 32;
        for (int k = t; k < 1024; k += 256) {
            int i = k & 31, r = k >> 5;
            float s = net_feat[(n0 + r) * 32 + i];
            nfp[i * 32 + r] = make_float2(s, s);
        }
        __syncthreads();

        int c  = t & 63;   // f4 cols c and c+64
        int rg = t >> 6;   // row group 0..3: rows rg*8 .. rg*8+7
        const float4* B4 = (const float4*)Bs;

        unsigned long long acc[32];
#pragma unroll
        for (int k = 0; k < 32; k++) acc[k] = 0ull;

        float4 bA = B4[c];
        float4 bB = B4[64 + c];
#pragma unroll
        for (int i = 0; i < 32; i++) {
            float4 nA = bA, nB = bB;
            if (i < 31) {
                nA = B4[(i + 1) * 128 + c];
                nB = B4[(i + 1) * 128 + 64 + c];
            }
            unsigned long long a01, a23, b01, b23;
            asm("mov.b64 %0, {%1, %2};" : "=l"(a01) : "f"(bA.x), "f"(bA.y));
            asm("mov.b64 %0, {%1, %2};" : "=l"(a23) : "f"(bA.z), "f"(bA.w));
            asm("mov.b64 %0, {%1, %2};" : "=l"(b01) : "f"(bB.x), "f"(bB.y));
            asm("mov.b64 %0, {%1, %2};" : "=l"(b23) : "f"(bB.z), "f"(bB.w));
            const ulonglong2* SPi = (const ulonglong2*)(nfp + i * 32 + rg * 8);
            ulonglong2 s0 = SPi[0], s1 = SPi[1], s2 = SPi[2], s3 = SPi[3];
#pragma unroll
            for (int j = 0; j < 4; j++) {
                ulonglong2 sv = (j == 0) ? s0 : (j == 1) ? s1 : (j == 2) ? s2 : s3;
                asm("fma.rn.f32x2 %0, %1, %2, %0;" : "+l"(acc[(2*j)  *4+0]) : "l"(sv.x), "l"(a01));
                asm("fma.rn.f32x2 %0, %1, %2, %0;" : "+l"(acc[(2*j)  *4+1]) : "l"(sv.x), "l"(a23));
                asm("fma.rn.f32x2 %0, %1, %2, %0;" : "+l"(acc[(2*j)  *4+2]) : "l"(sv.x), "l"(b01));
                asm("fma.rn.f32x2 %0, %1, %2, %0;" : "+l"(acc[(2*j)  *4+3]) : "l"(sv.x), "l"(b23));
                asm("fma.rn.f32x2 %0, %1, %2, %0;" : "+l"(acc[(2*j+1)*4+0]) : "l"(sv.y), "l"(a01));
                asm("fma.rn.f32x2 %0, %1, %2, %0;" : "+l"(acc[(2*j+1)*4+1]) : "l"(sv.y), "l"(a23));
                asm("fma.rn.f32x2 %0, %1, %2, %0;" : "+l"(acc[(2*j+1)*4+2]) : "l"(sv.y), "l"(b01));
                asm("fma.rn.f32x2 %0, %1, %2, %0;" : "+l"(acc[(2*j+1)*4+3]) : "l"(sv.y), "l"(b23));
            }
            bA = nA;
            bB = nB;
        }

#pragma unroll
        for (int r = 0; r < 8; r++) {
            float4 o0, o1;
            asm("mov.b64 {%0, %1}, %2;" : "=f"(o0.x), "=f"(o0.y) : "l"(acc[r * 4 + 0]));
            asm("mov.b64 {%0, %1}, %2;" : "=f"(o0.z), "=f"(o0.w) : "l"(acc[r * 4 + 1]));
            asm("mov.b64 {%0, %1}, %2;" : "=f"(o1.x), "=f"(o1.y) : "l"(acc[r * 4 + 2]));
            asm("mov.b64 {%0, %1}, %2;" : "=f"(o1.z), "=f"(o1.w) : "l"(acc[r * 4 + 3]));
            size_t row = (size_t)(n0 + rg * 8 + r) * 128;
            ((float4*)g_T)[row + c]      = o0;
            ((float4*)g_T)[row + 64 + c] = o1;
        }
    } else {
        cudaGridDependencySynchronize();      // PDL: g_start ready
        int e = (b - 625) * 256 + t;
        if (e >= NEDGE) return;
        int n = edge_net[e];
        int pos = g_start[n] + atomicAdd(&g_cursor[n], 1);
        g_sEdge[pos] = e;
        g_sNode[pos] = edge_node[e];
        g_sNet[pos]  = n;
    }
}

// ============ 4. edge (R9-proven per-edge parallel) + rel-1 segment sum ============
__global__ void __launch_bounds__(256) k_edgeagg(const float* __restrict__ pin_feat,
                                                 const float* __restrict__ node_feat,
                                                 float* __restrict__ out) {
    cudaGridDependencySynchronize();          // PDL: g_T + sorted arrays ready
    int b = blockIdx.x;
    int t = threadIdx.x;
    int lane = t & 31;
    if (b < 6250) {
        int warp = (b * 256 + t) >> 5;
        int g = lane >> 3, j = lane & 7;
        int s = warp * 4 + g;
        if (s >= NEDGE) return;
        int n = g_sNet[s];
        int v = g_sNode[s];
        int e = g_sEdge[s];
        const float4* Trow = ((const float4*)g_T) + (size_t)n * 128;
        float4 acc = ((const float4*)g_Bias)[n * 8 + j];
        const float4* pin4 = ((const float4*)pin_feat) + (size_t)e * 4;
#pragma unroll
        for (int q = 0; q < 4; q++) {
            float4 pv = pin4[q];
            float4 t0 = Trow[(4 * q + 0) * 8 + j];
            float4 t1 = Trow[(4 * q + 1) * 8 + j];
            float4 t2 = Trow[(4 * q + 2) * 8 + j];
            float4 t3 = Trow[(4 * q + 3) * 8 + j];
            acc.x += pv.x * t0.x + pv.y * t1.x + pv.z * t2.x + pv.w * t3.x;
            acc.y += pv.x * t0.y + pv.y * t1.y + pv.z * t2.y + pv.w * t3.y;
            acc.z += pv.x * t0.z + pv.y * t1.z + pv.z * t2.z + pv.w * t3.z;
            acc.w += pv.x * t0.w + pv.y * t1.w + pv.z * t2.w + pv.w * t3.w;
        }
        red_add_v4(out + (size_t)v * 32 + j * 4, acc);
    } else {
        int n = ((b - 6250) * 256 + t) >> 5;
        if (n >= N_NETS) return;
        int start = g_start[n], cnt = g_cnt[n];
        float ax = 0.f, ay = 0.f;
        const float2* nf2 = (const float2*)node_feat;
        int p = 0;
        while (p < cnt) {
            int m = min(cnt - p, 32);
            int v = 0; float scl = 0.f;           // lanes >= m: v=0, scl=0 (safe)
            if (lane < m) {
                v = g_sNode[start + p + lane];
                scl = rsqrtf(fmaxf(g_degN[v], 1.0f));
            }
            int mm = (m + 3) & ~3;
            for (int k = 0; k < mm; k += 4) {
                int v0 = __shfl_sync(0xffffffffu, v, k);
                int v1 = __shfl_sync(0xffffffffu, v, k + 1);
                int v2 = __shfl_sync(0xffffffffu, v, k + 2);
                int v3 = __shfl_sync(0xffffffffu, v, k + 3);
                float s0 = __shfl_sync(0xffffffffu, scl, k);
                float s1 = __shfl_sync(0xffffffffu, scl, k + 1);
                float s2 = __shfl_sync(0xffffffffu, scl, k + 2);
                float s3 = __shfl_sync(0xffffffffu, scl, k + 3);
                float2 x0 = nf2[(size_t)v0 * 32 + lane];
                float2 x1 = nf2[(size_t)v1 * 32 + lane];
                float2 x2 = nf2[(size_t)v2 * 32 + lane];
                float2 x3 = nf2[(size_t)v3 * 32 + lane];
                ax += s0 * x0.x + s1 * x1.x + s2 * x2.x + s3 * x3.x;
                ay += s0 * x0.y + s1 * x1.y + s2 * x2.y + s3 * x3.y;
            }
            p += m;
        }
        float si = rsqrtf(fmaxf((float)cnt, 1.0f));
        ((float2*)g_agg)[n * 32 + lane] = make_float2(ax * si, ay * si);
    }
}

// ============ 5. tail: net_out GEMM | finalize (+restore zero-invariant) ============
__global__ void __launch_bounds__(256) k_tail(const float* __restrict__ W1,
                                              const float* __restrict__ b1,
                                              const float* __restrict__ b_nn,
                                              float* __restrict__ out) {
    int b = blockIdx.x;
    int t = threadIdx.x;
    if (b < 2500) {
        __shared__ float W1s[64 * 64];
        __shared__ float b1s[64];
        for (int k = t; k < 4096; k += 256) W1s[k] = W1[k];   // indep of predecessor
        if (t < 64) b1s[t] = b1[t];
        cudaGridDependencySynchronize();      // PDL: g_agg ready
        __syncthreads();
        int lane = t & 31;
        int n = b * 8 + (t >> 5);
        if (n >= N_NETS) return;
        float* net_out = out + (size_t)N_NODE * 32;
        float a0 = g_agg[n * 64 + lane];
        float a1 = g_agg[n * 64 + 32 + lane];
        float acc0 = b1s[lane], acc1 = b1s[32 + lane];
#pragma unroll
        for (int k = 0; k < 32; k++) {
            float r = __shfl_sync(0xffffffffu, a0, k);
            acc0 += r * W1s[k * 64 + lane];
            acc1 += r * W1s[k * 64 + 32 + lane];
        }
#pragma unroll
        for (int k = 0; k < 32; k++) {
            float r = __shfl_sync(0xffffffffu, a1, k);
            acc0 += r * W1s[(k + 32) * 64 + lane];
            acc1 += r * W1s[(k + 32) * 64 + 32 + lane];
        }
        net_out[n * 64 + lane]      = acc0;
        net_out[n * 64 + 32 + lane] = acc1;
    } else if (b < 5625) {
        cudaGridDependencySynchronize();      // PDL: out accumulation done
        int idx = (b - 2500) * 256 + t;
        if (idx >= N_NODE * 8) return;
        int v = idx >> 3, j = idx & 7;
        float dn = g_degN[v];                 // warp-convergent read before j==0 store
        float inv = 1.0f / fmaxf(dn, 1.0f);
        float4 o = ((float4*)out)[idx];
        float4 bn = ((const float4*)b_nn)[j];
        o.x = o.x * inv + bn.x;
        o.y = o.y * inv + bn.y;
        o.z = o.z * inv + bn.z;
        o.w = o.w * inv + bn.w;
        ((float4*)out)[idx] = o;
        if (j == 0) g_degN[v] = 0.0f;         // restore invariant
    } else {
        cudaGridDependencySynchronize();      // k_mid's scatter cursor use done
        int i = (b - 5625) * 256 + t;         // 5000 f4 each
        float4 z = make_float4(0.f, 0.f, 0.f, 0.f);
        if (i < 5000)       ((float4*)g_cnt)[i] = z;
        else if (i < 10000) ((float4*)g_cursor)[i - 5000] = z;
    }
}

// helper: launch with PDL (programmatic stream serialization)
template <typename K, typename... Args>
static void launch_pdl(K kernel, dim3 grid, dim3 block, size_t smem, Args... args) {
    cudaLaunchConfig_t cfg = {};
    cfg.gridDim = grid;
    cfg.blockDim = block;
    cfg.dynamicSmemBytes = smem;
    cfg.stream = 0;
    cudaLaunchAttribute attr[1];
    attr[0].id = cudaLaunchAttributeProgrammaticStreamSerialization;
    attr[0].val.programmaticStreamSerializationAllowed = 1;
    cfg.attrs = attr;
    cfg.numAttrs = 1;
    cudaLaunchKernelEx(&cfg, kernel, args...);
}

extern "C" void kernel_launch(void* const* d_in, const int* in_sizes, int n_in,
                              void* d_out, int out_size) {
    const float* node_feat = (const float*)d_in[0];
    const float* net_feat  = (const float*)d_in[1];
    const float* pin_feat  = (const float*)d_in[2];
    const int*   edge_node = (const int*)d_in[3];
    const int*   edge_net  = (const int*)d_in[4];
    const float* W1   = (const float*)d_in[5];
    const float* b1   = (const float*)d_in[6];
    const float* W2   = (const float*)d_in[7];
    const float* b2   = (const float*)d_in[8];
    const float* b_nn = (const float*)d_in[9];
    float* out = (float*)d_out;

    cudaFuncSetAttribute(k_mid, cudaFuncAttributeMaxDynamicSharedMemorySize, 73728);

    k_degzero<<<6471, 256>>>(edge_node, edge_net, W2, net_feat, b2, out);
    launch_pdl(k_scan, dim3(1), dim3(1024), 0);
    launch_pdl(k_mid, dim3(1407), dim3(256), (size_t)73728, net_feat, edge_node, edge_net);
    launch_pdl(k_edgeagg, dim3(8750), dim3(256), (size_t)0, pin_feat, node_feat, out);
    launch_pdl(k_tail, dim3(5665), dim3(256), (size_t)0, W1, b1, b_nn, out);
}